// round 1
// baseline (speedup 1.0000x reference)
#include <cuda_runtime.h>

// Global accumulator (no device allocations allowed).
__device__ double g_acc;

__global__ void zero_acc_kernel() {
    g_acc = 0.0;
}

// Flat dot-product reduction over n elements (n4 = n/4 float4 pairs, plus tail).
__global__ void __launch_bounds__(256) dot_reduce_kernel(
    const float4* __restrict__ p4,
    const float4* __restrict__ c4,
    const float*  __restrict__ p,
    const float*  __restrict__ c,
    long long n4, long long n)
{
    float s = 0.0f;
    const long long stride = (long long)gridDim.x * blockDim.x;
    long long i = (long long)blockIdx.x * blockDim.x + threadIdx.x;

    // Main vectorized loop. Unroll for MLP (independent LDG.128 pairs in flight).
    #pragma unroll 4
    for (; i < n4; i += stride) {
        float4 a = p4[i];
        float4 b = c4[i];
        s += a.x * b.x;
        s += a.y * b.y;
        s += a.z * b.z;
        s += a.w * b.w;
    }

    // Scalar tail (n % 4 != 0 case; absent for this shape but kept for safety).
    for (long long j = 4 * n4 + ((long long)blockIdx.x * blockDim.x + threadIdx.x);
         j < n; j += stride) {
        s += p[j] * c[j];
    }

    // Warp reduction.
    #pragma unroll
    for (int o = 16; o > 0; o >>= 1)
        s += __shfl_xor_sync(0xffffffffu, s, o);

    // Block reduction via shared memory.
    __shared__ float warp_sums[8];  // 256 threads -> 8 warps
    const int lane = threadIdx.x & 31;
    const int wid  = threadIdx.x >> 5;
    if (lane == 0) warp_sums[wid] = s;
    __syncthreads();

    if (wid == 0) {
        s = (lane < 8) ? warp_sums[lane] : 0.0f;
        #pragma unroll
        for (int o = 4; o > 0; o >>= 1)
            s += __shfl_xor_sync(0xffffffffu, s, o);
        if (lane == 0)
            atomicAdd(&g_acc, (double)s);
    }
}

__global__ void finalize_kernel(float* __restrict__ out, double inv_rows) {
    *out = (float)(g_acc * inv_rows);
}

extern "C" void kernel_launch(void* const* d_in, const int* in_sizes, int n_in,
                              void* d_out, int out_size) {
    const float* probs     = (const float*)d_in[0];
    const float* centroids = (const float*)d_in[1];
    float* out = (float*)d_out;

    const long long n    = (long long)in_sizes[0];   // N*K = 101,000,000
    const long long rows = n / 101;                  // K = 101 bins per row
    const long long n4   = n >> 2;                   // exactly divisible for this shape

    zero_acc_kernel<<<1, 1>>>();

    const int threads = 256;
    // ~16 blocks per SM on 148 SMs: enough threads to saturate HBM with LDG.128.
    int blocks = 148 * 16;
    long long max_blocks = (n4 + threads - 1) / threads;
    if (blocks > max_blocks) blocks = (int)max_blocks;
    if (blocks < 1) blocks = 1;

    dot_reduce_kernel<<<blocks, threads>>>(
        (const float4*)probs, (const float4*)centroids,
        probs, centroids, n4, n);

    finalize_kernel<<<1, 1>>>(out, 1.0 / (double)rows);
}

// round 2
// speedup vs baseline: 1.0003x; 1.0003x over previous
#include <cuda_runtime.h>

// Scratch (device globals — no allocations allowed).
#define MAX_BLOCKS 4096
__device__ float        g_partials[MAX_BLOCKS];
__device__ unsigned int g_count = 0;   // self-resetting: 0 before every run

// Single fused kernel: grid-stride dot product + last-block final reduction.
__global__ void __launch_bounds__(256) fused_dot_mean_kernel(
    const float4* __restrict__ p4,
    const float4* __restrict__ c4,
    const float*  __restrict__ p,
    const float*  __restrict__ c,
    long long n4, long long n,
    float* __restrict__ out, double inv_rows)
{
    float s = 0.0f;
    const long long stride = (long long)gridDim.x * blockDim.x;
    long long i = (long long)blockIdx.x * blockDim.x + threadIdx.x;

    // Streaming loads (read-once data): evict-first hint, LDG.128 pairs.
    #pragma unroll 4
    for (; i < n4; i += stride) {
        float4 a = __ldcs(&p4[i]);
        float4 b = __ldcs(&c4[i]);
        s += a.x * b.x;
        s += a.y * b.y;
        s += a.z * b.z;
        s += a.w * b.w;
    }
    // Scalar tail (absent for this shape; kept for safety).
    for (long long j = 4 * n4 + ((long long)blockIdx.x * blockDim.x + threadIdx.x);
         j < n; j += stride)
        s += p[j] * c[j];

    // Warp reduction.
    #pragma unroll
    for (int o = 16; o > 0; o >>= 1)
        s += __shfl_xor_sync(0xffffffffu, s, o);

    __shared__ float wsum[8];
    const int lane = threadIdx.x & 31;
    const int wid  = threadIdx.x >> 5;
    if (lane == 0) wsum[wid] = s;
    __syncthreads();

    // Block partial -> global scratch; last block finishes the job.
    __shared__ bool is_last;
    if (threadIdx.x == 0) {
        float bs = 0.0f;
        #pragma unroll
        for (int w = 0; w < 8; w++) bs += wsum[w];
        g_partials[blockIdx.x] = bs;
        __threadfence();                      // make partial visible before count
        unsigned int t = atomicAdd(&g_count, 1u);
        is_last = (t == gridDim.x - 1);
    }
    __syncthreads();

    if (is_last) {
        __threadfence();                      // acquire all partials
        double d = 0.0;
        for (unsigned int k = threadIdx.x; k < gridDim.x; k += blockDim.x)
            d += (double)g_partials[k];

        #pragma unroll
        for (int o = 16; o > 0; o >>= 1)
            d += __shfl_xor_sync(0xffffffffu, d, o);

        __shared__ double dsum[8];
        if (lane == 0) dsum[wid] = d;
        __syncthreads();
        if (threadIdx.x == 0) {
            double tot = 0.0;
            #pragma unroll
            for (int w = 0; w < 8; w++) tot += dsum[w];
            *out = (float)(tot * inv_rows);
            g_count = 0;                      // reset for next graph replay
        }
    }
}

extern "C" void kernel_launch(void* const* d_in, const int* in_sizes, int n_in,
                              void* d_out, int out_size) {
    const float* probs     = (const float*)d_in[0];
    const float* centroids = (const float*)d_in[1];
    float* out = (float*)d_out;

    const long long n    = (long long)in_sizes[0];   // N*K = 101,000,000
    const long long rows = n / 101;                  // K = 101 bins per row
    const long long n4   = n >> 2;

    const int threads = 256;
    int blocks = 148 * 16;                           // 2368 — saturates HBM
    long long max_blocks = (n4 + threads - 1) / threads;
    if (blocks > max_blocks) blocks = (int)max_blocks;
    if (blocks > MAX_BLOCKS) blocks = MAX_BLOCKS;
    if (blocks < 1) blocks = 1;

    fused_dot_mean_kernel<<<blocks, threads>>>(
        (const float4*)probs, (const float4*)centroids,
        probs, centroids, n4, n, out, 1.0 / (double)rows);
}

// round 3
// speedup vs baseline: 1.0349x; 1.0347x over previous
#include <cuda_runtime.h>

#define MAX_BLOCKS 4096
__device__ float        g_partials[MAX_BLOCKS];
__device__ unsigned int g_count = 0;   // self-resetting: 0 before every run

// One full wave: 8 blocks/SM * 148 SMs, 256 threads.
__global__ void __launch_bounds__(256) fused_dot_mean_kernel(
    const float4* __restrict__ p4,
    const float4* __restrict__ c4,
    const float*  __restrict__ p,
    const float*  __restrict__ c,
    int n4, long long n,
    float* __restrict__ out, double inv_rows)
{
    float s = 0.0f;
    const int stride = gridDim.x * blockDim.x;          // int32 indexing
    const int tid0   = blockIdx.x * blockDim.x + threadIdx.x;

    // Main vectorized loop: unroll 8 -> up to 16 independent LDG.128 in flight.
    int i = tid0;
    #pragma unroll 8
    for (; i < n4; i += stride) {
        float4 a = __ldcs(&p4[i]);
        float4 b = __ldcs(&c4[i]);
        s += a.x * b.x;
        s += a.y * b.y;
        s += a.z * b.z;
        s += a.w * b.w;
    }

    // Scalar tail (absent for this shape; kept for safety).
    for (long long j = 4LL * n4 + tid0; j < n; j += stride)
        s += p[j] * c[j];

    // Warp reduction.
    #pragma unroll
    for (int o = 16; o > 0; o >>= 1)
        s += __shfl_xor_sync(0xffffffffu, s, o);

    __shared__ float wsum[8];
    const int lane = threadIdx.x & 31;
    const int wid  = threadIdx.x >> 5;
    if (lane == 0) wsum[wid] = s;
    __syncthreads();

    __shared__ bool is_last;
    if (threadIdx.x == 0) {
        float bs = 0.0f;
        #pragma unroll
        for (int w = 0; w < 8; w++) bs += wsum[w];
        g_partials[blockIdx.x] = bs;
        __threadfence();
        unsigned int t = atomicAdd(&g_count, 1u);
        is_last = (t == gridDim.x - 1);
    }
    __syncthreads();

    if (is_last) {
        __threadfence();
        double d = 0.0;
        for (unsigned int k = threadIdx.x; k < gridDim.x; k += blockDim.x)
            d += (double)g_partials[k];
        #pragma unroll
        for (int o = 16; o > 0; o >>= 1)
            d += __shfl_xor_sync(0xffffffffu, d, o);

        __shared__ double dsum[8];
        if (lane == 0) dsum[wid] = d;
        __syncthreads();
        if (threadIdx.x == 0) {
            double tot = 0.0;
            #pragma unroll
            for (int w = 0; w < 8; w++) tot += dsum[w];
            *out = (float)(tot * inv_rows);
            g_count = 0;   // reset for next graph replay
        }
    }
}

extern "C" void kernel_launch(void* const* d_in, const int* in_sizes, int n_in,
                              void* d_out, int out_size) {
    const float* probs     = (const float*)d_in[0];
    const float* centroids = (const float*)d_in[1];
    float* out = (float*)d_out;

    const long long n    = (long long)in_sizes[0];   // N*K = 101,000,000
    const long long rows = n / 101;                  // K = 101
    const int  n4        = (int)(n >> 2);            // 25,250,000 — fits int32

    const int threads = 256;
    int blocks = 148 * 8;                            // exactly one full wave
    long long max_blocks = ((long long)n4 + threads - 1) / threads;
    if (blocks > max_blocks) blocks = (int)max_blocks;
    if (blocks > MAX_BLOCKS) blocks = MAX_BLOCKS;
    if (blocks < 1) blocks = 1;

    fused_dot_mean_kernel<<<blocks, threads>>>(
        (const float4*)probs, (const float4*)centroids,
        probs, centroids, n4, n, out, 1.0 / (double)rows);
}